// round 9
// baseline (speedup 1.0000x reference)
#include <cuda_runtime.h>
#include <cooperative_groups.h>

namespace cg = cooperative_groups;

// PointPillars pseudo-image: fused init+scatter+gather in ONE cooperative
// kernel (two grid.sync()s replace two kernel-launch boundaries).
// Output: (B=16, C=64, NY=400, NX=400) float32 = 655 MB, fully written.

#define B_   16
#define C_   64
#define NY_  400
#define NX_  400
#define PLANE  (NY_ * NX_)      // 160,000 pixels per frame
#define NPIX   (B_ * PLANE)     // 2,560,000 total pixels

// pixel -> (local voxel index + 1), 0 = empty. 5.12 MB __device__ scratch.
__device__ unsigned short g_map[NPIX];

__global__ void __launch_bounds__(256) fused_kernel(
    const float* __restrict__ feat, const int* __restrict__ idx,
    float* __restrict__ out, int n_vox, int nvb)
{
    cg::grid_group grid = cg::this_grid();
    const int tid      = blockIdx.x * blockDim.x + threadIdx.x;
    const int nthreads = gridDim.x * blockDim.x;

    // ---- phase 1: init map to 0 (int4 stores: 8 u16 entries each) ----
    for (int i = tid; i < NPIX / 8; i += nthreads) {
        reinterpret_cast<int4*>(g_map)[i] = make_int4(0, 0, 0, 0);
    }
    grid.sync();

    // ---- phase 2: scatter local voxel ids (+1); unique cells, no races ----
    for (int i = tid; i < n_vox; i += nthreads) {
        int4 v = reinterpret_cast<const int4*>(idx)[i];     // (b, z, y, x)
        int local = i - v.x * nvb;                          // index within batch
        g_map[v.x * PLANE + v.z * NX_ + v.w] = (unsigned short)(local + 1);
    }
    grid.sync();

    // ---- phase 3: gather — EXACT R3 body (proven local optimum), outer
    //      loop grid-strided. Consecutive tid -> consecutive quads, so the
    //      per-warp coalescing (512 B per channel-store) is unchanged. ----
    const float4 zero = make_float4(0.f, 0.f, 0.f, 0.f);

    for (int q = tid; q < NPIX / 4; q += nthreads) {
        int p   = q * 4;                                    // flat pixel index
        int b   = p / PLANE;
        int rem = p - b * PLANE;                            // quad-aligned offset

        ushort4 mv = *reinterpret_cast<const ushort4*>(g_map + p);
        int m0 = (int)mv.x, m1 = (int)mv.y, m2 = (int)mv.z, m3 = (int)mv.w;

        long long base = (long long)b * nvb - 1;            // row = base + m (m>0)
        const float* f0 = feat + (base + m0) * C_;
        const float* f1 = feat + (base + m1) * C_;
        const float* f2 = feat + (base + m2) * C_;
        const float* f3 = feat + (base + m3) * C_;

        float* obase = out + (long long)b * C_ * PLANE + rem;

#pragma unroll 4
        for (int c = 0; c < C_; c += 4) {
            float4 a0 = (m0 > 0) ? *reinterpret_cast<const float4*>(f0 + c) : zero;
            float4 a1 = (m1 > 0) ? *reinterpret_cast<const float4*>(f1 + c) : zero;
            float4 a2 = (m2 > 0) ? *reinterpret_cast<const float4*>(f2 + c) : zero;
            float4 a3 = (m3 > 0) ? *reinterpret_cast<const float4*>(f3 + c) : zero;

            float4 o;
            o.x = a0.x; o.y = a1.x; o.z = a2.x; o.w = a3.x;
            *reinterpret_cast<float4*>(obase + (long long)(c + 0) * PLANE) = o;
            o.x = a0.y; o.y = a1.y; o.z = a2.y; o.w = a3.y;
            *reinterpret_cast<float4*>(obase + (long long)(c + 1) * PLANE) = o;
            o.x = a0.z; o.y = a1.z; o.z = a2.z; o.w = a3.z;
            *reinterpret_cast<float4*>(obase + (long long)(c + 2) * PLANE) = o;
            o.x = a0.w; o.y = a1.w; o.z = a2.w; o.w = a3.w;
            *reinterpret_cast<float4*>(obase + (long long)(c + 3) * PLANE) = o;
        }
    }
}

// ---------------------------------------------------------------------------
// launch: one cooperative kernel node. Grid sized for guaranteed co-residency
// via the occupancy API (host-side queries; capture-safe, no allocations).
// ---------------------------------------------------------------------------
extern "C" void kernel_launch(void* const* d_in, const int* in_sizes, int n_in,
                              void* d_out, int out_size) {
    const float* feat = (const float*)d_in[0];      // (N, 64) float32
    const int*   idx  = (const int*)d_in[1];        // (N, 4)  int32
    float*       out  = (float*)d_out;              // (16, 64, 400, 400)

    int n_vox = in_sizes[1] / 4;
    int nvb   = n_vox / B_;                         // voxels per batch frame

    int dev = 0;
    cudaGetDevice(&dev);
    int nsm = 0;
    cudaDeviceGetAttribute(&nsm, cudaDevAttrMultiProcessorCount, dev);
    int blocks_per_sm = 0;
    cudaOccupancyMaxActiveBlocksPerMultiprocessor(
        &blocks_per_sm, (const void*)fused_kernel, 256, 0);
    if (blocks_per_sm < 1) blocks_per_sm = 1;

    dim3 grid((unsigned)(nsm * blocks_per_sm));
    dim3 block(256);

    void* args[] = { (void*)&feat, (void*)&idx, (void*)&out,
                     (void*)&n_vox, (void*)&nvb };
    cudaLaunchCooperativeKernel((const void*)fused_kernel, grid, block, args, 0, 0);
}

// round 10
// speedup vs baseline: 1.1740x; 1.1740x over previous
#include <cuda_runtime.h>

// PointPillars pseudo-image: inverse-map (u16) + coalesced gather.
// Output: (B=16, C=64, NY=400, NX=400) float32 = 655 MB, fully written each call.
//
// Structure = R3 (best known: 119.2us) with ONE change: the map-init kernel
// launch is replaced by a cudaMemsetAsync graph node (no kernel ramp).

#define B_   16
#define C_   64
#define NY_  400
#define NX_  400
#define PLANE  (NY_ * NX_)      // 160,000 pixels per frame
#define NPIX   (B_ * PLANE)     // 2,560,000 total pixels

// pixel -> (local voxel index + 1), 0 = empty. 5.12 MB __device__ scratch.
__device__ unsigned short g_map[NPIX];

// ---------------------------------------------------------------------------
// 1) scatter local voxel ids (+1) into the map (unique cells -> no races)
// ---------------------------------------------------------------------------
__global__ void scatter_map_kernel(const int* __restrict__ idx, int n, int nvb) {
    int i = blockIdx.x * blockDim.x + threadIdx.x;
    if (i < n) {
        int4 v = reinterpret_cast<const int4*>(idx)[i];  // (b, z, y, x)
        int local = i - v.x * nvb;                       // index within batch
        g_map[v.x * PLANE + v.z * NX_ + v.w] = (unsigned short)(local + 1);
    }
}

// ---------------------------------------------------------------------------
// 2) gather: EXACT R3 body and launch shape (proven local optimum).
//    One thread per quad of 4 consecutive x-pixels, 64 channels in chunks
//    of 4; predicated feature loads, 512B-coalesced warp stores per channel.
// ---------------------------------------------------------------------------
__global__ void __launch_bounds__(256) gather_kernel(
    const float* __restrict__ feat, float* __restrict__ out, int nvb)
{
    int q = blockIdx.x * blockDim.x + threadIdx.x;   // quad id
    if (q >= NPIX / 4) return;

    int p   = q * 4;                                 // flat pixel index
    int b   = p / PLANE;
    int rem = p - b * PLANE;                         // quad-aligned offset in plane

    ushort4 mv = *reinterpret_cast<const ushort4*>(g_map + p);
    int m0 = (int)mv.x, m1 = (int)mv.y, m2 = (int)mv.z, m3 = (int)mv.w;

    long long base = (long long)b * nvb - 1;         // row = base + m (when m>0)
    const float* f0 = feat + (base + m0) * C_;
    const float* f1 = feat + (base + m1) * C_;
    const float* f2 = feat + (base + m2) * C_;
    const float* f3 = feat + (base + m3) * C_;

    float* obase = out + (long long)b * C_ * PLANE + rem;
    const float4 zero = make_float4(0.f, 0.f, 0.f, 0.f);

#pragma unroll 4
    for (int c = 0; c < C_; c += 4) {
        float4 a0 = (m0 > 0) ? *reinterpret_cast<const float4*>(f0 + c) : zero;
        float4 a1 = (m1 > 0) ? *reinterpret_cast<const float4*>(f1 + c) : zero;
        float4 a2 = (m2 > 0) ? *reinterpret_cast<const float4*>(f2 + c) : zero;
        float4 a3 = (m3 > 0) ? *reinterpret_cast<const float4*>(f3 + c) : zero;

        float4 o;
        o.x = a0.x; o.y = a1.x; o.z = a2.x; o.w = a3.x;
        *reinterpret_cast<float4*>(obase + (long long)(c + 0) * PLANE) = o;
        o.x = a0.y; o.y = a1.y; o.z = a2.y; o.w = a3.y;
        *reinterpret_cast<float4*>(obase + (long long)(c + 1) * PLANE) = o;
        o.x = a0.z; o.y = a1.z; o.z = a2.z; o.w = a3.z;
        *reinterpret_cast<float4*>(obase + (long long)(c + 2) * PLANE) = o;
        o.x = a0.w; o.y = a1.w; o.z = a2.w; o.w = a3.w;
        *reinterpret_cast<float4*>(obase + (long long)(c + 3) * PLANE) = o;
    }
}

// ---------------------------------------------------------------------------
// launch: memset node (map=0) -> scatter -> gather
// ---------------------------------------------------------------------------
extern "C" void kernel_launch(void* const* d_in, const int* in_sizes, int n_in,
                              void* d_out, int out_size) {
    const float* feat = (const float*)d_in[0];      // (N, 64) float32
    const int*   idx  = (const int*)d_in[1];        // (N, 4)  int32
    float*       out  = (float*)d_out;              // (16, 64, 400, 400)

    int n_vox = in_sizes[1] / 4;
    int nvb   = n_vox / B_;                         // voxels per batch frame

    void* map_ptr = nullptr;
    cudaGetSymbolAddress(&map_ptr, g_map);          // host-side query, capture-safe

    cudaMemsetAsync(map_ptr, 0, NPIX * sizeof(unsigned short), 0);
    scatter_map_kernel<<<(n_vox + 255) / 256, 256>>>(idx, n_vox, nvb);
    gather_kernel<<<(NPIX / 4 + 255) / 256, 256>>>(feat, out, nvb);
}